// round 9
// baseline (speedup 1.0000x reference)
#include <cuda_runtime.h>
#include <cuda_fp16.h>

// ---------------------------------------------------------------------------
// ShiftedWindowAttention: B=32, H=W=64, C=256, HEADS=8, HD=32, WS=8, SHIFT=4
// R8: tcgen05 unavailable (harness PTX target = compute_103 w/o 'a').
//     HMMA path optimized instead:
//       - qkv/out gemms: 3-stage cp.async ring, ONE __syncthreads per stage
//       - attn: precomputed fp16 bias+mask table (4 win types x 8 heads)
// ---------------------------------------------------------------------------

#define WIN_TOT 2048
#define SCALE_F 0.17677669529663687f
#define PANEL 8192              // halves per 128x64 tile (16KB)

__device__ __half g_q  [(size_t)WIN_TOT * 8 * 64 * 32];
__device__ __half g_k  [(size_t)WIN_TOT * 8 * 64 * 32];
__device__ __half g_v  [(size_t)WIN_TOT * 8 * 64 * 32];
__device__ __half g_att[(size_t)WIN_TOT * 64 * 256];
__device__ __half g_wqkv[768 * 256];
__device__ __half g_wout[256 * 256];
__device__ __half g_biast[4 * 8 * 64 * 64];   // [type][head][q][k] bias+mask

// ---------------- mma / ldmatrix helpers ----------------
__device__ __forceinline__ void mma_16816(float c[4], const unsigned a[4],
                                          unsigned b0, unsigned b1) {
    asm volatile(
        "mma.sync.aligned.m16n8k16.row.col.f32.f16.f16.f32 "
        "{%0,%1,%2,%3}, {%4,%5,%6,%7}, {%8,%9}, {%0,%1,%2,%3};\n"
        : "+f"(c[0]), "+f"(c[1]), "+f"(c[2]), "+f"(c[3])
        : "r"(a[0]), "r"(a[1]), "r"(a[2]), "r"(a[3]), "r"(b0), "r"(b1));
}
__device__ __forceinline__ void ldsm_x4(unsigned r[4], const __half* p) {
    unsigned addr = (unsigned)__cvta_generic_to_shared(p);
    asm volatile("ldmatrix.sync.aligned.m8n8.x4.shared.b16 {%0,%1,%2,%3}, [%4];"
                 : "=r"(r[0]), "=r"(r[1]), "=r"(r[2]), "=r"(r[3]) : "r"(addr));
}
__device__ __forceinline__ void ldsm_x4_t(unsigned r[4], const __half* p) {
    unsigned addr = (unsigned)__cvta_generic_to_shared(p);
    asm volatile("ldmatrix.sync.aligned.m8n8.x4.trans.shared.b16 {%0,%1,%2,%3}, [%4];"
                 : "=r"(r[0]), "=r"(r[1]), "=r"(r[2]), "=r"(r[3]) : "r"(addr));
}
__device__ __forceinline__ const __half* swaddr(const __half* base, int row, int colh) {
    return base + row * 64 + ((((colh >> 3) ^ (row & 7))) << 3);
}
__device__ __forceinline__ void ldA_sw(unsigned r[4], const __half* base,
                                       int r0, int c0, int lane) {
    int lr = lane & 7, sel = lane >> 3;
    ldsm_x4(r, swaddr(base, r0 + lr + (sel & 1) * 8, c0 + ((sel >> 1) * 8)));
}
__device__ __forceinline__ void ldB_sw(unsigned r[4], const __half* base,
                                       int n0, int k0, int lane) {
    int lr = lane & 7, sel = lane >> 3;
    ldsm_x4(r, swaddr(base, n0 + lr + ((sel >> 1) * 8), k0 + ((sel & 1) * 8)));
}
__device__ __forceinline__ void ldfragA(unsigned r[4], const __half* t, int ld,
                                        int r0, int c0, int lane) {
    int lr = lane & 7, sel = lane >> 3;
    ldsm_x4(r, t + (r0 + lr + (sel & 1) * 8) * ld + c0 + ((sel >> 1) * 8));
}
__device__ __forceinline__ void ldfragB(unsigned r[4], const __half* t, int ld,
                                        int n0, int k0, int lane) {
    int lr = lane & 7, sel = lane >> 3;
    ldsm_x4(r, t + (n0 + lr + ((sel >> 1) * 8)) * ld + k0 + ((sel & 1) * 8));
}
__device__ __forceinline__ void ldfragBT(unsigned r[4], const __half* t, int ld,
                                         int k0, int n0, int lane) {
    int lr = lane & 7, sel = lane >> 3;
    ldsm_x4_t(r, t + (k0 + lr + ((sel & 1) * 8)) * ld + n0 + ((sel >> 1) * 8));
}
__device__ __forceinline__ unsigned packh2(float x, float y) {
    __half2 h = __floats2half2_rn(x, y);
    return *reinterpret_cast<unsigned*>(&h);
}
__device__ __forceinline__ void cp16(void* s, const void* g) {
    unsigned sa = (unsigned)__cvta_generic_to_shared(s);
    asm volatile("cp.async.cg.shared.global [%0], [%1], 16;" :: "r"(sa), "l"(g));
}
__device__ __forceinline__ void cp_commit() {
    asm volatile("cp.async.commit_group;");
}

// ---------------- prep ----------------
__global__ void prep_weights(const float* __restrict__ wqkv,
                             const float* __restrict__ wout) {
    int i = blockIdx.x * blockDim.x + threadIdx.x;
    if (i < 768 * 256) g_wqkv[i] = __float2half(wqkv[i]);
    if (i < 256 * 256) g_wout[i] = __float2half(wout[i]);
}

// bias+mask table: type = (wy==7)*2 + (wx==7)
__global__ void prep_bias(const float* __restrict__ pos_enc) {
    int t = blockIdx.x >> 3, h = blockIdx.x & 7;
    int q = threadIdx.x;               // 64 threads
    int qy = q >> 3, qx = q & 7;
    int wy7 = t >> 1, wx7 = t & 1;
    int rqy = wy7 ? ((qy < 4) ? 1 : 2) : 0;
    int rqx = wx7 ? ((qx < 4) ? 1 : 2) : 0;
    int rq = rqy * 3 + rqx;
    const float* pe = pos_enc + h * 225;
    __half* dst = g_biast + (((size_t)(t * 8 + h) * 64) + q) * 64;
    for (int k = 0; k < 64; k++) {
        int ky = k >> 3, kx = k & 7;
        int rky = wy7 ? ((ky < 4) ? 1 : 2) : 0;
        int rkx = wx7 ? ((kx < 4) ? 1 : 2) : 0;
        float v = pe[(qy - ky + 7) * 15 + (qx - kx + 7)];
        if (rq != rky * 3 + rkx) v = -30000.0f;
        dst[k] = __float2half(v);
    }
}

// ---------------- QKV GEMM: A stationary, B 3-stage ring ----------------
// grid (1024): bm. A = gathered 128x256 (4 panels, 64KB). B streamed over
// 24 stages (nt 0..5, kt 0..3) of 128x64 (16KB) in a 3-buffer ring, one
// __syncthreads per stage. smem 112KB -> 2 CTAs/SM.
#define SMEM_PROJ3 (7 * PANEL * 2)   // 114688 bytes

__device__ __forceinline__ void qkv_loadB(__half* Bp, int ss, int tid) {
    int nnt = ss >> 2, nkt = ss & 3;
    #pragma unroll
    for (int i = tid; i < 1024; i += 256) {
        int r = i >> 3, c = i & 7;
        cp16(Bp + r * 64 + ((c ^ (r & 7)) * 8),
             g_wqkv + (size_t)(nnt * 128 + r) * 256 + nkt * 64 + c * 8);
    }
    cp_commit();
}

__global__ __launch_bounds__(256, 2) void qkv_gemm(const float* __restrict__ x,
                                                   const float* __restrict__ bqkv) {
    extern __shared__ __half sm[];
    __half* Ast  = sm;               // 4 stationary panels
    __half* Bbuf = sm + 4 * PANEL;   // 3-buffer ring
    int tid = threadIdx.x, bm = blockIdx.x;

    // prologue: B stages 0,1 -> bufs 0,1
    qkv_loadB(Bbuf,          0, tid);
    qkv_loadB(Bbuf + PANEL,  1, tid);

    // stationary A: shifted-window gather, fp32 -> fp16, swizzled panels
    for (int i = tid; i < 4096; i += 256) {
        int r = i >> 5, ch = i & 31, p = ch >> 3, c = ch & 7;
        int rowg = bm * 128 + r;
        int win = rowg >> 6, tok = rowg & 63;
        int b = win >> 6, w = win & 63;
        int gy = (((w >> 3) << 3) + (tok >> 3) + 4) & 63;
        int gx = (((w & 7) << 3) + (tok & 7) + 4) & 63;
        const float4* src = reinterpret_cast<const float4*>(
            x + ((size_t)(b * 4096 + gy * 64 + gx)) * 256) + p * 16 + c * 2;
        float4 v0 = src[0], v1 = src[1];
        __half2* d2 = reinterpret_cast<__half2*>(
            Ast + p * PANEL + r * 64 + ((c ^ (r & 7)) * 8));
        d2[0] = __floats2half2_rn(v0.x, v0.y);
        d2[1] = __floats2half2_rn(v0.z, v0.w);
        d2[2] = __floats2half2_rn(v1.x, v1.y);
        d2[3] = __floats2half2_rn(v1.z, v1.w);
    }

    int warp = tid >> 5, lane = tid & 31;
    int wm = warp >> 1, wn = warp & 1;
    int lr4 = lane >> 2, lc2 = (lane & 3) * 2;

    for (int nt = 0; nt < 6; nt++) {
        float acc[2][8][4];
        #pragma unroll
        for (int i = 0; i < 2; i++)
            #pragma unroll
            for (int j = 0; j < 8; j++)
                #pragma unroll
                for (int e = 0; e < 4; e++) acc[i][j][e] = 0.f;

        #pragma unroll
        for (int kt = 0; kt < 4; kt++) {
            int ss = nt * 4 + kt;
            if (ss < 23) asm volatile("cp.async.wait_group 1;" ::: "memory");
            else         asm volatile("cp.async.wait_group 0;" ::: "memory");
            __syncthreads();
            if (ss + 2 < 24)
                qkv_loadB(Bbuf + ((ss + 2) % 3) * PANEL, ss + 2, tid);

            const __half* Ap = Ast + kt * PANEL;
            const __half* Bp = Bbuf + (ss % 3) * PANEL;
            #pragma unroll
            for (int kk = 0; kk < 4; kk++) {
                unsigned a0[4], a1[4];
                ldA_sw(a0, Ap, wm * 32,      kk * 16, lane);
                ldA_sw(a1, Ap, wm * 32 + 16, kk * 16, lane);
                #pragma unroll
                for (int j = 0; j < 4; j++) {
                    unsigned b[4];
                    ldB_sw(b, Bp, wn * 64 + j * 16, kk * 16, lane);
                    mma_16816(acc[0][2 * j],     a0, b[0], b[1]);
                    mma_16816(acc[0][2 * j + 1], a0, b[2], b[3]);
                    mma_16816(acc[1][2 * j],     a1, b[0], b[1]);
                    mma_16816(acc[1][2 * j + 1], a1, b[2], b[3]);
                }
            }
        }

        int which = nt >> 1;
        __half* basep = (which == 0) ? g_q : ((which == 1) ? g_k : g_v);
        float scl = (which == 0) ? SCALE_F : 1.0f;
        #pragma unroll
        for (int i = 0; i < 2; i++) {
            #pragma unroll
            for (int j = 0; j < 8; j++) {
                int c256 = (nt & 1) * 128 + wn * 64 + j * 8 + lc2;
                int hd = c256 >> 5, d = c256 & 31;
                float bb0 = bqkv[which * 256 + c256];
                float bb1 = bqkv[which * 256 + c256 + 1];
                #pragma unroll
                for (int r = 0; r < 2; r++) {
                    int rowg = bm * 128 + wm * 32 + i * 16 + lr4 + r * 8;
                    int win = rowg >> 6, tok = rowg & 63;
                    float v0 = (acc[i][j][r * 2 + 0] + bb0) * scl;
                    float v1 = (acc[i][j][r * 2 + 1] + bb1) * scl;
                    *reinterpret_cast<__half2*>(
                        basep + (((size_t)(win * 8 + hd) * 64 + tok) * 32 + d)) =
                        __floats2half2_rn(v0, v1);
                }
            }
        }
    }
}

// ---------------- attention: 1 CTA = (window, head), 2 warps ----------------
#define LDW 40
#define BSTR 72
__global__ __launch_bounds__(64) void attn_kernel() {
    __shared__ __half qs[64 * LDW];
    __shared__ __half ks[64 * LDW];
    __shared__ __half vs[64 * LDW];
    __shared__ __half bs[64 * BSTR];   // bias+mask tile, padded rows

    int tid = threadIdx.x;
    int h = blockIdx.x, win = blockIdx.y;
    int w = win & 63, wy = w >> 3, wx = w & 7;
    int ty_ = ((wy == 7) ? 2 : 0) + ((wx == 7) ? 1 : 0);

    size_t base = ((size_t)win * 8 + h) * 64 * 32;
    const int4* gq = reinterpret_cast<const int4*>(g_q + base);
    const int4* gk = reinterpret_cast<const int4*>(g_k + base);
    const int4* gv = reinterpret_cast<const int4*>(g_v + base);
    #pragma unroll
    for (int i = tid; i < 256; i += 64) {
        int row = i >> 2, s4 = i & 3;
        int doff = row * LDW + s4 * 8;
        *reinterpret_cast<int4*>(qs + doff) = gq[i];
        *reinterpret_cast<int4*>(ks + doff) = gk[i];
        *reinterpret_cast<int4*>(vs + doff) = gv[i];
    }
    const int4* gb = reinterpret_cast<const int4*>(
        g_biast + ((size_t)(ty_ * 8 + h) << 12));
    #pragma unroll
    for (int i = tid; i < 512; i += 64) {
        int r = i >> 3, c = i & 7;
        *reinterpret_cast<int4*>(bs + r * BSTR + c * 8) = gb[i];
    }
    __syncthreads();

    int warp = tid >> 5, lane = tid & 31;
    int lr4 = lane >> 2, lc2 = (lane & 3) * 2;

    #pragma unroll
    for (int si = 0; si < 2; si++) {
        int s = warp * 2 + si;
        float sa[8][4];
        #pragma unroll
        for (int nt = 0; nt < 8; nt++)
            #pragma unroll
            for (int e = 0; e < 4; e++) sa[nt][e] = 0.f;

        unsigned qa0[4], qa1[4];
        ldfragA(qa0, qs, LDW, s * 16, 0,  lane);
        ldfragA(qa1, qs, LDW, s * 16, 16, lane);
        #pragma unroll
        for (int np = 0; np < 4; np++) {
            unsigned kb0[4], kb1[4];
            ldfragB(kb0, ks, LDW, np * 16, 0,  lane);
            ldfragB(kb1, ks, LDW, np * 16, 16, lane);
            mma_16816(sa[2 * np],     qa0, kb0[0], kb0[1]);
            mma_16816(sa[2 * np + 1], qa0, kb0[2], kb0[3]);
            mma_16816(sa[2 * np],     qa1, kb1[0], kb1[1]);
            mma_16816(sa[2 * np + 1], qa1, kb1[2], kb1[3]);
        }

        int q0 = s * 16 + lr4, q1 = q0 + 8;
        const __half* b0 = bs + q0 * BSTR;
        const __half* b1 = bs + q1 * BSTR;
        float m0 = -1e30f, m1 = -1e30f;
        #pragma unroll
        for (int nt = 0; nt < 8; nt++) {
            __half2 u0 = *reinterpret_cast<const __half2*>(b0 + nt * 8 + lc2);
            __half2 u1 = *reinterpret_cast<const __half2*>(b1 + nt * 8 + lc2);
            float2 f0 = __half22float2(u0), f1 = __half22float2(u1);
            float v0 = sa[nt][0] + f0.x, v1 = sa[nt][1] + f0.y;
            sa[nt][0] = v0; sa[nt][1] = v1;
            m0 = fmaxf(m0, fmaxf(v0, v1));
            float w0 = sa[nt][2] + f1.x, w1 = sa[nt][3] + f1.y;
            sa[nt][2] = w0; sa[nt][3] = w1;
            m1 = fmaxf(m1, fmaxf(w0, w1));
        }
        m0 = fmaxf(m0, __shfl_xor_sync(0xffffffffu, m0, 1));
        m0 = fmaxf(m0, __shfl_xor_sync(0xffffffffu, m0, 2));
        m1 = fmaxf(m1, __shfl_xor_sync(0xffffffffu, m1, 1));
        m1 = fmaxf(m1, __shfl_xor_sync(0xffffffffu, m1, 2));
        float l0 = 0.f, l1 = 0.f;
        #pragma unroll
        for (int nt = 0; nt < 8; nt++) {
            float p0 = __expf(sa[nt][0] - m0); sa[nt][0] = p0; l0 += p0;
            float p1 = __expf(sa[nt][1] - m0); sa[nt][1] = p1; l0 += p1;
            float p2 = __expf(sa[nt][2] - m1); sa[nt][2] = p2; l1 += p2;
            float p3 = __expf(sa[nt][3] - m1); sa[nt][3] = p3; l1 += p3;
        }
        l0 += __shfl_xor_sync(0xffffffffu, l0, 1);
        l0 += __shfl_xor_sync(0xffffffffu, l0, 2);
        l1 += __shfl_xor_sync(0xffffffffu, l1, 1);
        l1 += __shfl_xor_sync(0xffffffffu, l1, 2);
        float il0 = 1.0f / l0, il1 = 1.0f / l1;

        float oa[4][4];
        #pragma unroll
        for (int j = 0; j < 4; j++)
            #pragma unroll
            for (int e = 0; e < 4; e++) oa[j][e] = 0.f;
        #pragma unroll
        for (int ksx = 0; ksx < 4; ksx++) {
            unsigned pa[4];
            pa[0] = packh2(sa[2 * ksx][0],     sa[2 * ksx][1]);
            pa[1] = packh2(sa[2 * ksx][2],     sa[2 * ksx][3]);
            pa[2] = packh2(sa[2 * ksx + 1][0], sa[2 * ksx + 1][1]);
            pa[3] = packh2(sa[2 * ksx + 1][2], sa[2 * ksx + 1][3]);
            unsigned vb[4];
            ldfragBT(vb, vs, LDW, ksx * 16, 0, lane);
            mma_16816(oa[0], pa, vb[0], vb[1]);
            mma_16816(oa[1], pa, vb[2], vb[3]);
            ldfragBT(vb, vs, LDW, ksx * 16, 16, lane);
            mma_16816(oa[2], pa, vb[0], vb[1]);
            mma_16816(oa[3], pa, vb[2], vb[3]);
        }
        #pragma unroll
        for (int j = 0; j < 4; j++) {
            int d = j * 8 + lc2;
            __half2 w0 = __floats2half2_rn(oa[j][0] * il0, oa[j][1] * il0);
            __half2 w1 = __floats2half2_rn(oa[j][2] * il1, oa[j][3] * il1);
            *reinterpret_cast<__half2*>(g_att + ((size_t)(win * 64 + q0) * 256) + h * 32 + d) = w0;
            *reinterpret_cast<__half2*>(g_att + ((size_t)(win * 64 + q1) * 256) + h * 32 + d) = w1;
        }
    }
}

// ---------------- out proj: B stationary, A 3-stage ring; scatter ----------
__device__ __forceinline__ void out_loadA(__half* Ap, int bm, int kt, int tid) {
    #pragma unroll
    for (int i = tid; i < 1024; i += 256) {
        int r = i >> 3, c = i & 7;
        cp16(Ap + r * 64 + ((c ^ (r & 7)) * 8),
             g_att + (size_t)(bm * 128 + r) * 256 + kt * 64 + c * 8);
    }
    cp_commit();
}

__global__ __launch_bounds__(256, 2) void out_gemm(const float* __restrict__ bout,
                                                   float* __restrict__ out) {
    extern __shared__ __half sm2[];
    __half* Bst  = sm2;              // 4 stationary panels (wout slice)
    __half* Abuf = sm2 + 4 * PANEL;  // 3-buffer ring (g_att)
    int tid = threadIdx.x, bm = blockIdx.x, bn = blockIdx.y;

    out_loadA(Abuf,         bm, 0, tid);
    out_loadA(Abuf + PANEL, bm, 1, tid);

    for (int i = tid; i < 4096; i += 256) {
        int r = i >> 5, ch = i & 31, p = ch >> 3, c = ch & 7;
        int4 v = *reinterpret_cast<const int4*>(
            g_wout + (size_t)(bn * 128 + r) * 256 + p * 64 + c * 8);
        *reinterpret_cast<int4*>(Bst + p * PANEL + r * 64 + ((c ^ (r & 7)) * 8)) = v;
    }

    int warp = tid >> 5, lane = tid & 31;
    int wm = warp >> 1, wn = warp & 1;
    float acc[2][8][4];
    #pragma unroll
    for (int i = 0; i < 2; i++)
        #pragma unroll
        for (int j = 0; j < 8; j++)
            #pragma unroll
            for (int e = 0; e < 4; e++) acc[i][j][e] = 0.f;

    #pragma unroll
    for (int kt = 0; kt < 4; kt++) {
        if (kt < 3) asm volatile("cp.async.wait_group 1;" ::: "memory");
        else        asm volatile("cp.async.wait_group 0;" ::: "memory");
        __syncthreads();
        if (kt + 2 < 4) out_loadA(Abuf + ((kt + 2) % 3) * PANEL, bm, kt + 2, tid);

        const __half* Ap = Abuf + (kt % 3) * PANEL;
        const __half* Bp = Bst + kt * PANEL;
        #pragma unroll
        for (int kk = 0; kk < 4; kk++) {
            unsigned a0[4], a1[4];
            ldA_sw(a0, Ap, wm * 32,      kk * 16, lane);
            ldA_sw(a1, Ap, wm * 32 + 16, kk * 16, lane);
            #pragma unroll
            for (int j = 0; j < 4; j++) {
                unsigned b[4];
                ldB_sw(b, Bp, wn * 64 + j * 16, kk * 16, lane);
                mma_16816(acc[0][2 * j],     a0, b[0], b[1]);
                mma_16816(acc[0][2 * j + 1], a0, b[2], b[3]);
                mma_16816(acc[1][2 * j],     a1, b[0], b[1]);
                mma_16816(acc[1][2 * j + 1], a1, b[2], b[3]);
            }
        }
    }

    int lr4 = lane >> 2, lc2 = (lane & 3) * 2;
    #pragma unroll
    for (int i = 0; i < 2; i++) {
        #pragma unroll
        for (int j = 0; j < 8; j++) {
            int col = bn * 128 + wn * 64 + j * 8 + lc2;
            float bb0 = bout[col], bb1 = bout[col + 1];
            #pragma unroll
            for (int r = 0; r < 2; r++) {
                int rowg = bm * 128 + wm * 32 + i * 16 + lr4 + r * 8;
                int win = rowg >> 6, w = rowg & 63;
                int tok = w;
                int wb = win >> 6, ww = win & 63;
                int wy = ww >> 3, wx = ww & 7;
                int ty = tok >> 3, tx = tok & 7;
                int gy = ((wy << 3) + ty + 4) & 63;
                int gx = ((wx << 3) + tx + 4) & 63;
                float2 v;
                v.x = acc[i][j][r * 2 + 0] + bb0;
                v.y = acc[i][j][r * 2 + 1] + bb1;
                *reinterpret_cast<float2*>(
                    out + ((size_t)(wb * 4096 + gy * 64 + gx)) * 256 + col) = v;
            }
        }
    }
}

// ---------------- launch ----------------
extern "C" void kernel_launch(void* const* d_in, const int* in_sizes, int n_in,
                              void* d_out, int out_size) {
    const float* x     = (const float*)d_in[0];
    const float* wqkv  = (const float*)d_in[1];
    const float* bqkv  = (const float*)d_in[2];
    const float* wout  = (const float*)d_in[3];
    const float* bout  = (const float*)d_in[4];
    const float* penc  = (const float*)d_in[5];
    float* out = (float*)d_out;

    cudaFuncSetAttribute((const void*)qkv_gemm, cudaFuncAttributeMaxDynamicSharedMemorySize, SMEM_PROJ3);
    cudaFuncSetAttribute((const void*)out_gemm, cudaFuncAttributeMaxDynamicSharedMemorySize, SMEM_PROJ3);

    prep_weights<<<768, 256>>>(wqkv, wout);
    prep_bias<<<32, 64>>>(penc);
    qkv_gemm<<<1024, 256, SMEM_PROJ3>>>(x, bqkv);
    attn_kernel<<<dim3(8, WIN_TOT), 64>>>();
    out_gemm<<<dim3(1024, 2), 256, SMEM_PROJ3>>>(bout, out);
}